// round 15
// baseline (speedup 1.0000x reference)
#include <cuda_runtime.h>

#define MAX_NODES 100000
#define MAX_EDGES 1600000
#define D 64
#define EPS 1e-9f

#define SCAN_TILE 1024
#define MAX_SCAN_BLOCKS 128

// Scratch (no allocations allowed -> device globals)
static __device__ int   g_count[MAX_NODES];
static __device__ int   g_offset[MAX_NODES];
static __device__ int   g_rank[MAX_EDGES];      // per-edge rank within its row
static __device__ int   g_blockSums[MAX_SCAN_BLOCKS];  // RAW per-block sums
static __device__ int2  g_edges[MAX_EDGES];     // (col, val-as-int) CSR-sorted
static __device__ float g_WT0[D * D];           // W0^T  [k][j]
static __device__ float g_WT1[D * D];           // W1^T  [k][j]

// ---- packed f32x2 helpers (sm_100+) ----
__device__ __forceinline__ unsigned long long fma2(unsigned long long a,
                                                   unsigned long long b,
                                                   unsigned long long c) {
    unsigned long long d;
    asm("fma.rn.f32x2 %0, %1, %2, %3;" : "=l"(d) : "l"(a), "l"(b), "l"(c));
    return d;
}
__device__ __forceinline__ unsigned long long pack2(float a) {
    unsigned long long r;
    asm("mov.b64 %0, {%1, %1};" : "=l"(r) : "f"(a));
    return r;
}
__device__ __forceinline__ void unpack2(unsigned long long v, float& lo, float& hi) {
    asm("mov.b64 {%0, %1}, %2;" : "=f"(lo), "=f"(hi) : "l"(v));
}

// ---------------------------------------------------------------------------
// Kernel 0: transpose weights + zero counters (merged)
// ---------------------------------------------------------------------------
__global__ void prep_kernel(const float* __restrict__ W0,
                            const float* __restrict__ W1, int nNodes) {
    int gid = blockIdx.x * blockDim.x + threadIdx.x;
    if (gid < D * D) {
        int j = gid >> 6, k = gid & 63;
        g_WT0[k * 64 + j] = W0[gid];
        g_WT1[k * 64 + j] = W1[gid];
    }
    for (int i = gid; i < nNodes; i += gridDim.x * blockDim.x)
        g_count[i] = 0;
}

// ---------------------------------------------------------------------------
// Kernel 1: histogram of edge_row; atomic returns the edge's rank
// ---------------------------------------------------------------------------
__global__ void hist_kernel(const int* __restrict__ edge_row, int E) {
    int e = blockIdx.x * blockDim.x + threadIdx.x;
    if (e < E) g_rank[e] = atomicAdd(&g_count[__ldg(edge_row + e)], 1);
}

// ---------------------------------------------------------------------------
// Scan phase A: per-block sum of SCAN_TILE counts (raw sums)
// ---------------------------------------------------------------------------
__global__ __launch_bounds__(256)
void scan_reduce_kernel(int nNodes) {
    __shared__ int warpSums[8];
    int b = blockIdx.x;
    int base = b * SCAN_TILE + threadIdx.x * 4;

    int s = 0;
    if (base + 3 < nNodes) {
        int4 v = *reinterpret_cast<const int4*>(g_count + base);
        s = v.x + v.y + v.z + v.w;
    } else {
        for (int i = 0; i < 4; ++i)
            if (base + i < nNodes) s += g_count[base + i];
    }
    #pragma unroll
    for (int off = 16; off; off >>= 1)
        s += __shfl_xor_sync(0xffffffffu, s, off);
    int lane = threadIdx.x & 31, warp = threadIdx.x >> 5;
    if (lane == 0) warpSums[warp] = s;
    __syncthreads();
    if (threadIdx.x == 0) {
        int t = 0;
        #pragma unroll
        for (int w = 0; w < 8; ++w) t += warpSums[w];
        g_blockSums[b] = t;
    }
}

// ---------------------------------------------------------------------------
// Scan phase B+C merged: per-block prefix of raw sums + write offsets
// ---------------------------------------------------------------------------
__global__ __launch_bounds__(256)
void scan_write_kernel(int nNodes, int nBlocks) {
    __shared__ int warpSums[8];
    __shared__ int sBS[MAX_SCAN_BLOCKS];
    int b = blockIdx.x;
    int tid = threadIdx.x;

    if (tid < nBlocks) sBS[tid] = g_blockSums[tid];
    __syncthreads();
    int blockPrefix = 0;
    for (int i = 0; i < b; ++i) blockPrefix += sBS[i];

    int base = b * SCAN_TILE + tid * 4;

    int c[4] = {0, 0, 0, 0};
    if (base + 3 < nNodes) {
        int4 v = *reinterpret_cast<const int4*>(g_count + base);
        c[0] = v.x; c[1] = v.y; c[2] = v.z; c[3] = v.w;
    } else {
        for (int i = 0; i < 4; ++i)
            if (base + i < nNodes) c[i] = g_count[base + i];
    }
    int local = c[0] + c[1] + c[2] + c[3];

    int lane = tid & 31, warp = tid >> 5;
    int p = local;
    #pragma unroll
    for (int off = 1; off < 32; off <<= 1) {
        int t = __shfl_up_sync(0xffffffffu, p, off);
        if (lane >= off) p += t;
    }
    if (lane == 31) warpSums[warp] = p;
    __syncthreads();
    int warpBase = 0;
    for (int w = 0; w < warp; ++w) warpBase += warpSums[w];
    int run = blockPrefix + warpBase + (p - local);

    int o[4];
    o[0] = run;
    o[1] = o[0] + c[0];
    o[2] = o[1] + c[1];
    o[3] = o[2] + c[2];
    if (base + 3 < nNodes) {
        *reinterpret_cast<int4*>(g_offset + base) = make_int4(o[0], o[1], o[2], o[3]);
    } else {
        for (int i = 0; i < 4; ++i)
            if (base + i < nNodes) g_offset[base + i] = o[i];
    }
}

// ---------------------------------------------------------------------------
// Kernel 4: scatter edges into CSR order — atomic-free, 4 edges/thread
// ---------------------------------------------------------------------------
__global__ __launch_bounds__(256)
void edge_scatter_kernel(const int* __restrict__ edge_row,
                         const int* __restrict__ edge_col,
                         const float* __restrict__ edge_val,
                         int E) {
    int t = blockIdx.x * blockDim.x + threadIdx.x;
    int e = t * 4;
    if (e + 3 < E) {
        int4 r4 = __ldg(reinterpret_cast<const int4*>(edge_row + e));
        int4 k4 = __ldg(reinterpret_cast<const int4*>(g_rank + e));
        int4 c4 = __ldg(reinterpret_cast<const int4*>(edge_col + e));
        float4 v4 = __ldg(reinterpret_cast<const float4*>(edge_val + e));
        int p0 = __ldg(&g_offset[r4.x]) + k4.x;
        int p1 = __ldg(&g_offset[r4.y]) + k4.y;
        int p2 = __ldg(&g_offset[r4.z]) + k4.z;
        int p3 = __ldg(&g_offset[r4.w]) + k4.w;
        g_edges[p0] = make_int2(c4.x, __float_as_int(v4.x));
        g_edges[p1] = make_int2(c4.y, __float_as_int(v4.y));
        g_edges[p2] = make_int2(c4.z, __float_as_int(v4.z));
        g_edges[p3] = make_int2(c4.w, __float_as_int(v4.w));
    } else {
        for (int i = e; i < E; ++i) {
            int r = __ldg(edge_row + i);
            int pos = __ldg(&g_offset[r]) + g_rank[i];
            g_edges[pos] = make_int2(__ldg(edge_col + i),
                                     __float_as_int(__ldg(edge_val + i)));
        }
    }
}

// ---------------------------------------------------------------------------
// Kernel 5: FUSED dual hop transform + in-block gather.
//   128 threads, 64 nodes/block.
//   Phase A: W0 + x tile -> smem; GEMM hop0 + norm -> r0 regs.
//   Phase B: W1 -> sW; GATHER agg for the 64 nodes directly into sA
//            (2 threads/node, 32 feats each, 8 indep LDG.128 per edge).
//   Phase C: GEMM hop1 + norm + combine + store.
// ---------------------------------------------------------------------------
#define ASTRIDE 68

__global__ __launch_bounds__(128)
void transform_kernel(const float* __restrict__ x,
                      const float* __restrict__ b0, const float* __restrict__ s0,
                      const float* __restrict__ o0,
                      const float* __restrict__ b1, const float* __restrict__ s1,
                      const float* __restrict__ o1,
                      float* __restrict__ out, int nNodes) {
    __shared__ float sA[64 * ASTRIDE];
    __shared__ float sW[64 * ASTRIDE];
    __shared__ float sPar[6 * D];

    int tid = threadIdx.x;
    int nodeBase = blockIdx.x * 64;

    for (int idx = tid; idx < 6 * D; idx += 128) {
        int which = idx >> 6, t = idx & 63;
        const float* src = (which == 0) ? b0 : (which == 1) ? s0 : (which == 2) ? o0
                         : (which == 3) ? b1 : (which == 4) ? s1 : o1;
        sPar[idx] = src[t];
    }
    {
        const float4* w4 = reinterpret_cast<const float4*>(g_WT0);
        for (int idx = tid; idx < 64 * 16; idx += 128) {
            int k = idx >> 4, c = idx & 15;
            *reinterpret_cast<float4*>(sW + k * ASTRIDE + c * 4) = __ldg(&w4[idx]);
        }
        const float4* x4 = reinterpret_cast<const float4*>(x);
        for (int idx = tid; idx < 64 * 16; idx += 128) {
            int node = idx >> 4, q = idx & 15;
            int gnode = nodeBase + node;
            float4 v = make_float4(0.f, 0.f, 0.f, 0.f);
            if (gnode < nNodes) v = __ldg(&x4[gnode * 16 + q]);
            *reinterpret_cast<float4*>(sA + node * ASTRIDE + q * 4) = v;
        }
    }
    __syncthreads();

    int f = tid & 7;
    int g = tid >> 3;          // 0..15, nodes g*4 .. g*4+3

    float r0[4][8];
    // ---------------- GEMM hop 0 (f32x2) ----------------
    {
        unsigned long long acc2[4][4];
        #pragma unroll
        for (int i = 0; i < 4; ++i)
            #pragma unroll
            for (int j = 0; j < 4; ++j) acc2[i][j] = 0ull;

        #pragma unroll 2
        for (int k4 = 0; k4 < 16; ++k4) {
            float4 av[4];
            #pragma unroll
            for (int i = 0; i < 4; ++i)
                av[i] = *reinterpret_cast<const float4*>(sA + (g * 4 + i) * ASTRIDE + k4 * 4);
            #pragma unroll
            for (int kk = 0; kk < 4; ++kk) {
                int k = k4 * 4 + kk;
                ulonglong2 wl = *reinterpret_cast<const ulonglong2*>(sW + k * ASTRIDE + f * 4);
                ulonglong2 wh = *reinterpret_cast<const ulonglong2*>(sW + k * ASTRIDE + 32 + f * 4);
                #pragma unroll
                for (int i = 0; i < 4; ++i) {
                    float a = (kk == 0) ? av[i].x : (kk == 1) ? av[i].y
                            : (kk == 2) ? av[i].z : av[i].w;
                    unsigned long long pa = pack2(a);
                    acc2[i][0] = fma2(pa, wl.x, acc2[i][0]);
                    acc2[i][1] = fma2(pa, wl.y, acc2[i][1]);
                    acc2[i][2] = fma2(pa, wh.x, acc2[i][2]);
                    acc2[i][3] = fma2(pa, wh.y, acc2[i][3]);
                }
            }
        }
        const float* bb = sPar;
        const float* sc = sPar + 64;
        const float* of = sPar + 128;
        #pragma unroll
        for (int i = 0; i < 4; ++i) {
            float acc[8];
            unpack2(acc2[i][0], acc[0], acc[1]);
            unpack2(acc2[i][1], acc[2], acc[3]);
            unpack2(acc2[i][2], acc[4], acc[5]);
            unpack2(acc2[i][3], acc[6], acc[7]);
            float s = 0.f, q = 0.f;
            #pragma unroll
            for (int j = 0; j < 8; ++j) {
                int feat = (j < 4) ? (f * 4 + j) : (32 + f * 4 + j - 4);
                float h = fmaxf(acc[j] + bb[feat], 0.f);
                acc[j] = h;
                s += h;
                q = fmaf(h, h, q);
            }
            #pragma unroll
            for (int off = 1; off < 8; off <<= 1) {
                s += __shfl_xor_sync(0xffffffffu, s, off);
                q += __shfl_xor_sync(0xffffffffu, q, off);
            }
            float mean = s * (1.0f / 64.0f);
            float var  = q * (1.0f / 64.0f) - mean * mean + EPS;
            float rinv = rsqrtf(var);
            #pragma unroll
            for (int j = 0; j < 8; ++j) {
                int feat = (j < 4) ? (f * 4 + j) : (32 + f * 4 + j - 4);
                r0[i][j] = (acc[j] - mean) * sc[feat] * rinv + of[feat];
            }
        }
    }
    __syncthreads();

    // ---------------- Phase B: W1 -> sW, in-block gather -> sA ----------------
    {
        const float4* w4 = reinterpret_cast<const float4*>(g_WT1);
        for (int idx = tid; idx < 64 * 16; idx += 128) {
            int k = idx >> 4, c = idx & 15;
            *reinterpret_cast<float4*>(sW + k * ASTRIDE + c * 4) = __ldg(&w4[idx]);
        }

        // gather: 2 threads per node, 32 feats (8 float4) per thread
        int node = tid >> 1;       // 0..63
        int h = tid & 1;           // feature half
        int gnode = nodeBase + node;
        float4 acc[8];
        #pragma unroll
        for (int i = 0; i < 8; ++i) acc[i] = make_float4(0.f, 0.f, 0.f, 0.f);
        if (gnode < nNodes) {
            int start = g_offset[gnode];
            int cnt   = g_count[gnode];
            const float4* x4 = reinterpret_cast<const float4*>(x);
            for (int e = 0; e < cnt; ++e) {
                int2 ev = __ldg(&g_edges[start + e]);
                float v = __int_as_float(ev.y);
                const float4* xr = x4 + (size_t)ev.x * 16 + h * 8;
                #pragma unroll
                for (int i = 0; i < 8; ++i) {
                    float4 xv = __ldg(xr + i);
                    acc[i].x = fmaf(v, xv.x, acc[i].x);
                    acc[i].y = fmaf(v, xv.y, acc[i].y);
                    acc[i].z = fmaf(v, xv.z, acc[i].z);
                    acc[i].w = fmaf(v, xv.w, acc[i].w);
                }
            }
        }
        float* dst = sA + node * ASTRIDE + h * 32;
        #pragma unroll
        for (int i = 0; i < 8; ++i)
            *reinterpret_cast<float4*>(dst + i * 4) = acc[i];
    }
    __syncthreads();

    // ---------------- GEMM hop 1 (f32x2) + combine + store ----------------
    {
        unsigned long long acc2[4][4];
        #pragma unroll
        for (int i = 0; i < 4; ++i)
            #pragma unroll
            for (int j = 0; j < 4; ++j) acc2[i][j] = 0ull;

        #pragma unroll 2
        for (int k4 = 0; k4 < 16; ++k4) {
            float4 av[4];
            #pragma unroll
            for (int i = 0; i < 4; ++i)
                av[i] = *reinterpret_cast<const float4*>(sA + (g * 4 + i) * ASTRIDE + k4 * 4);
            #pragma unroll
            for (int kk = 0; kk < 4; ++kk) {
                int k = k4 * 4 + kk;
                ulonglong2 wl = *reinterpret_cast<const ulonglong2*>(sW + k * ASTRIDE + f * 4);
                ulonglong2 wh = *reinterpret_cast<const ulonglong2*>(sW + k * ASTRIDE + 32 + f * 4);
                #pragma unroll
                for (int i = 0; i < 4; ++i) {
                    float a = (kk == 0) ? av[i].x : (kk == 1) ? av[i].y
                            : (kk == 2) ? av[i].z : av[i].w;
                    unsigned long long pa = pack2(a);
                    acc2[i][0] = fma2(pa, wl.x, acc2[i][0]);
                    acc2[i][1] = fma2(pa, wl.y, acc2[i][1]);
                    acc2[i][2] = fma2(pa, wh.x, acc2[i][2]);
                    acc2[i][3] = fma2(pa, wh.y, acc2[i][3]);
                }
            }
        }
        const float* bb = sPar + 192;
        const float* sc = sPar + 256;
        const float* of = sPar + 320;
        #pragma unroll
        for (int i = 0; i < 4; ++i) {
            float acc[8];
            unpack2(acc2[i][0], acc[0], acc[1]);
            unpack2(acc2[i][1], acc[2], acc[3]);
            unpack2(acc2[i][2], acc[4], acc[5]);
            unpack2(acc2[i][3], acc[6], acc[7]);
            float s = 0.f, q = 0.f;
            #pragma unroll
            for (int j = 0; j < 8; ++j) {
                int feat = (j < 4) ? (f * 4 + j) : (32 + f * 4 + j - 4);
                float h = fmaxf(acc[j] + bb[feat], 0.f);
                acc[j] = h;
                s += h;
                q = fmaf(h, h, q);
            }
            #pragma unroll
            for (int off = 1; off < 8; off <<= 1) {
                s += __shfl_xor_sync(0xffffffffu, s, off);
                q += __shfl_xor_sync(0xffffffffu, q, off);
            }
            float mean = s * (1.0f / 64.0f);
            float var  = q * (1.0f / 64.0f) - mean * mean + EPS;
            float rinv = rsqrtf(var);

            int gnode = nodeBase + g * 4 + i;
            if (gnode < nNodes) {
                float lo[4], hi[4];
                #pragma unroll
                for (int j = 0; j < 4; ++j) {
                    int feat = f * 4 + j;
                    lo[j] = r0[i][j] + (acc[j] - mean) * sc[feat] * rinv + of[feat];
                }
                #pragma unroll
                for (int j = 0; j < 4; ++j) {
                    int feat = 32 + f * 4 + j;
                    hi[j] = r0[i][4 + j] + (acc[4 + j] - mean) * sc[feat] * rinv + of[feat];
                }
                float* op = out + (size_t)gnode * D;
                *reinterpret_cast<float4*>(op + f * 4)      = make_float4(lo[0], lo[1], lo[2], lo[3]);
                *reinterpret_cast<float4*>(op + 32 + f * 4) = make_float4(hi[0], hi[1], hi[2], hi[3]);
            }
        }
    }
}

// ---------------------------------------------------------------------------
// Launch
// ---------------------------------------------------------------------------
extern "C" void kernel_launch(void* const* d_in, const int* in_sizes, int n_in,
                              void* d_out, int out_size) {
    const float* x        = (const float*)d_in[0];
    const float* edge_val = (const float*)d_in[1];
    const float* W0       = (const float*)d_in[2];
    const float* b0       = (const float*)d_in[3];
    const float* scale0   = (const float*)d_in[4];
    const float* offset0  = (const float*)d_in[5];
    const float* W1       = (const float*)d_in[6];
    const float* b1       = (const float*)d_in[7];
    const float* scale1   = (const float*)d_in[8];
    const float* offset1  = (const float*)d_in[9];
    const int*   edge_row = (const int*)d_in[10];
    const int*   edge_col = (const int*)d_in[11];
    float* out = (float*)d_out;

    int nNodes = in_sizes[0] / D;
    int E = in_sizes[1];

    prep_kernel<<<64, 256>>>(W0, W1, nNodes);
    hist_kernel<<<(E + 255) / 256, 256>>>(edge_row, E);

    int nScanBlocks = (nNodes + SCAN_TILE - 1) / SCAN_TILE;
    scan_reduce_kernel<<<nScanBlocks, 256>>>(nNodes);
    scan_write_kernel<<<nScanBlocks, 256>>>(nNodes, nScanBlocks);

    int nScatterThreads = (E + 3) / 4;
    edge_scatter_kernel<<<(nScatterThreads + 255) / 256, 256>>>(edge_row, edge_col,
                                                                edge_val, E);

    int grid_t = (nNodes + 63) / 64;
    transform_kernel<<<grid_t, 128>>>(x, b0, scale0, offset0,
                                      b1, scale1, offset1, out, nNodes);
}

// round 16
// speedup vs baseline: 1.3292x; 1.3292x over previous
#include <cuda_runtime.h>

#define MAX_NODES 100000
#define MAX_EDGES 1600000
#define D 64
#define EPS 1e-9f

#define SCAN_TILE 1024
#define MAX_SCAN_BLOCKS 128

// Scratch (no allocations allowed -> device globals; zero-initialized at load)
static __device__ int   g_count[MAX_NODES];
static __device__ int   g_offset[MAX_NODES];
static __device__ int   g_rank[MAX_EDGES];      // per-edge rank within its row
static __device__ int   g_blockSums[MAX_SCAN_BLOCKS];
static __device__ int   g_scanReady;            // spin-barrier counters
static __device__ int   g_scanDone;
static __device__ int2  g_edges[MAX_EDGES];     // (col, val-as-int) CSR-sorted
static __device__ float g_agg[MAX_NODES * D];   // aggregated features
static __device__ float g_WT0[D * D];           // W0^T  [k][j]
static __device__ float g_WT1[D * D];           // W1^T  [k][j]

// ---- packed f32x2 helpers (sm_100+) ----
__device__ __forceinline__ unsigned long long fma2(unsigned long long a,
                                                   unsigned long long b,
                                                   unsigned long long c) {
    unsigned long long d;
    asm("fma.rn.f32x2 %0, %1, %2, %3;" : "=l"(d) : "l"(a), "l"(b), "l"(c));
    return d;
}
__device__ __forceinline__ unsigned long long pack2(float a) {
    unsigned long long r;
    asm("mov.b64 %0, {%1, %1};" : "=l"(r) : "f"(a));
    return r;
}
__device__ __forceinline__ void unpack2(unsigned long long v, float& lo, float& hi) {
    asm("mov.b64 {%0, %1}, %2;" : "=f"(lo), "=f"(hi) : "l"(v));
}

// ---------------------------------------------------------------------------
// Kernel 1: histogram of edge_row, 4 edges/thread; atomic returns edge rank.
//   g_count arrives zeroed (module-load zero-init; re-zeroed by gather_kernel
//   at the end of every run).
// ---------------------------------------------------------------------------
__global__ __launch_bounds__(256)
void hist_kernel(const int* __restrict__ edge_row, int E) {
    int t = blockIdx.x * blockDim.x + threadIdx.x;
    int e = t * 4;
    if (e + 3 < E) {
        int4 r4 = __ldg(reinterpret_cast<const int4*>(edge_row + e));
        int4 k4;
        k4.x = atomicAdd(&g_count[r4.x], 1);
        k4.y = atomicAdd(&g_count[r4.y], 1);
        k4.z = atomicAdd(&g_count[r4.z], 1);
        k4.w = atomicAdd(&g_count[r4.w], 1);
        *reinterpret_cast<int4*>(g_rank + e) = k4;
    } else {
        for (int i = e; i < E; ++i)
            g_rank[i] = atomicAdd(&g_count[__ldg(edge_row + i)], 1);
    }
}

// ---------------------------------------------------------------------------
// Kernel 2: merged scan (reduce + device-wide spin barrier + write offsets).
//   Also folds the W transpose into blocks 0..15.
//   Grid MUST be nBlocks = ceil(nNodes/1024) = 98 <= 148 SMs -> co-resident.
// ---------------------------------------------------------------------------
__global__ __launch_bounds__(256)
void scan_kernel(const float* __restrict__ W0, const float* __restrict__ W1,
                 int nNodes, int nBlocks) {
    __shared__ int warpSums[8];
    __shared__ int sBS[MAX_SCAN_BLOCKS];
    int b = blockIdx.x;
    int tid = threadIdx.x;

    // fold weight transpose into the first 16 blocks (4096 elems, 256/block)
    if (b < 16) {
        int gid = b * 256 + tid;
        int j = gid >> 6, k = gid & 63;
        g_WT0[k * 64 + j] = __ldg(W0 + gid);
        g_WT1[k * 64 + j] = __ldg(W1 + gid);
    }

    int base = b * SCAN_TILE + tid * 4;
    int c[4] = {0, 0, 0, 0};
    if (base + 3 < nNodes) {
        int4 v = *reinterpret_cast<const int4*>(g_count + base);
        c[0] = v.x; c[1] = v.y; c[2] = v.z; c[3] = v.w;
    } else {
        for (int i = 0; i < 4; ++i)
            if (base + i < nNodes) c[i] = g_count[base + i];
    }
    int local = c[0] + c[1] + c[2] + c[3];

    int lane = tid & 31, warp = tid >> 5;
    int p = local;
    #pragma unroll
    for (int off = 1; off < 32; off <<= 1) {
        int t = __shfl_up_sync(0xffffffffu, p, off);
        if (lane >= off) p += t;
    }
    if (lane == 31) warpSums[warp] = p;
    __syncthreads();

    // publish block total, then device-wide spin barrier
    if (tid == 0) {
        int tot = 0;
        #pragma unroll
        for (int w = 0; w < 8; ++w) tot += warpSums[w];
        g_blockSums[b] = tot;
        __threadfence();
        atomicAdd(&g_scanReady, 1);
        while (atomicAdd(&g_scanReady, 0) < nBlocks) { }
    }
    __syncthreads();

    // all block sums now visible; read via volatile (bypass L1)
    if (tid < nBlocks) sBS[tid] = *(volatile int*)&g_blockSums[tid];
    __syncthreads();
    int blockPrefix = 0;
    for (int i = 0; i < b; ++i) blockPrefix += sBS[i];

    int warpBase = 0;
    for (int w = 0; w < warp; ++w) warpBase += warpSums[w];
    int run = blockPrefix + warpBase + (p - local);

    int o[4];
    o[0] = run;
    o[1] = o[0] + c[0];
    o[2] = o[1] + c[1];
    o[3] = o[2] + c[2];
    if (base + 3 < nNodes) {
        *reinterpret_cast<int4*>(g_offset + base) = make_int4(o[0], o[1], o[2], o[3]);
    } else {
        for (int i = 0; i < 4; ++i)
            if (base + i < nNodes) g_offset[base + i] = o[i];
    }

    // reset barrier counters for the next graph replay (last finisher only)
    __syncthreads();
    if (tid == 0) {
        int d = atomicAdd(&g_scanDone, 1);
        if (d == nBlocks - 1) { g_scanReady = 0; g_scanDone = 0; }
    }
}

// ---------------------------------------------------------------------------
// Kernel 3: scatter edges into CSR order — atomic-free, 4 edges/thread
// ---------------------------------------------------------------------------
__global__ __launch_bounds__(256)
void edge_scatter_kernel(const int* __restrict__ edge_row,
                         const int* __restrict__ edge_col,
                         const float* __restrict__ edge_val,
                         int E) {
    int t = blockIdx.x * blockDim.x + threadIdx.x;
    int e = t * 4;
    if (e + 3 < E) {
        int4 r4 = __ldg(reinterpret_cast<const int4*>(edge_row + e));
        int4 k4 = __ldg(reinterpret_cast<const int4*>(g_rank + e));
        int4 c4 = __ldg(reinterpret_cast<const int4*>(edge_col + e));
        float4 v4 = __ldg(reinterpret_cast<const float4*>(edge_val + e));
        int p0 = __ldg(&g_offset[r4.x]) + k4.x;
        int p1 = __ldg(&g_offset[r4.y]) + k4.y;
        int p2 = __ldg(&g_offset[r4.z]) + k4.z;
        int p3 = __ldg(&g_offset[r4.w]) + k4.w;
        g_edges[p0] = make_int2(c4.x, __float_as_int(v4.x));
        g_edges[p1] = make_int2(c4.y, __float_as_int(v4.y));
        g_edges[p2] = make_int2(c4.z, __float_as_int(v4.z));
        g_edges[p3] = make_int2(c4.w, __float_as_int(v4.w));
    } else {
        for (int i = e; i < E; ++i) {
            int r = __ldg(edge_row + i);
            int pos = __ldg(&g_offset[r]) + g_rank[i];
            g_edges[pos] = make_int2(__ldg(edge_col + i),
                                     __float_as_int(__ldg(edge_val + i)));
        }
    }
}

// ---------------------------------------------------------------------------
// Kernel 4: gather-SpMM.  8 threads/node (one warp octet), 8 feats each.
//   Also re-zeros g_count for the next run (p==0 thread per node).
// ---------------------------------------------------------------------------
__global__ __launch_bounds__(256)
void gather_kernel(const float* __restrict__ x, int nNodes) {
    int gid = blockIdx.x * 256 + threadIdx.x;
    int node = gid >> 3;
    int p = gid & 7;
    if (node >= nNodes) return;

    int lane = threadIdx.x & 31;
    unsigned gmask = 0xFFu << (lane & 24);

    int start = g_offset[node];
    int cnt   = g_count[node];
    if (p == 0) g_count[node] = 0;      // reset for next replay
    const float4* x4 = reinterpret_cast<const float4*>(x);

    float4 acc0 = make_float4(0.f, 0.f, 0.f, 0.f);
    float4 acc1 = make_float4(0.f, 0.f, 0.f, 0.f);

    for (int base = 0; base < cnt; base += 8) {
        int idx = base + p;
        int2 ev = (idx < cnt) ? __ldg(&g_edges[start + idx]) : make_int2(0, 0);
        int m = cnt - base; if (m > 8) m = 8;
        #pragma unroll 4
        for (int t = 0; t < m; ++t) {
            int   col = __shfl_sync(gmask, ev.x, t, 8);
            float v   = __int_as_float(__shfl_sync(gmask, ev.y, t, 8));
            float4 a = __ldg(&x4[col * 16 + p * 2]);
            float4 b = __ldg(&x4[col * 16 + p * 2 + 1]);
            acc0.x = fmaf(v, a.x, acc0.x); acc0.y = fmaf(v, a.y, acc0.y);
            acc0.z = fmaf(v, a.z, acc0.z); acc0.w = fmaf(v, a.w, acc0.w);
            acc1.x = fmaf(v, b.x, acc1.x); acc1.y = fmaf(v, b.y, acc1.y);
            acc1.z = fmaf(v, b.z, acc1.z); acc1.w = fmaf(v, b.w, acc1.w);
        }
    }

    float4* dst = reinterpret_cast<float4*>(g_agg + node * D + p * 8);
    dst[0] = acc0;
    dst[1] = acc1;
}

// ---------------------------------------------------------------------------
// Kernel 5: dual hop transform with packed f32x2 FMA (R12 version).
// ---------------------------------------------------------------------------
#define ASTRIDE 68

__global__ __launch_bounds__(128)
void transform_kernel(const float* __restrict__ x,
                      const float* __restrict__ b0, const float* __restrict__ s0,
                      const float* __restrict__ o0,
                      const float* __restrict__ b1, const float* __restrict__ s1,
                      const float* __restrict__ o1,
                      float* __restrict__ out, int nNodes) {
    __shared__ float sA[64 * ASTRIDE];
    __shared__ float sW[64 * ASTRIDE];
    __shared__ float sPar[6 * D];

    int tid = threadIdx.x;
    int nodeBase = blockIdx.x * 64;

    for (int idx = tid; idx < 6 * D; idx += 128) {
        int which = idx >> 6, t = idx & 63;
        const float* src = (which == 0) ? b0 : (which == 1) ? s0 : (which == 2) ? o0
                         : (which == 3) ? b1 : (which == 4) ? s1 : o1;
        sPar[idx] = src[t];
    }
    {
        const float4* w4 = reinterpret_cast<const float4*>(g_WT0);
        for (int idx = tid; idx < 64 * 16; idx += 128) {
            int k = idx >> 4, c = idx & 15;
            *reinterpret_cast<float4*>(sW + k * ASTRIDE + c * 4) = __ldg(&w4[idx]);
        }
        const float4* x4 = reinterpret_cast<const float4*>(x);
        for (int idx = tid; idx < 64 * 16; idx += 128) {
            int node = idx >> 4, q = idx & 15;
            int gnode = nodeBase + node;
            float4 v = make_float4(0.f, 0.f, 0.f, 0.f);
            if (gnode < nNodes) v = __ldg(&x4[gnode * 16 + q]);
            *reinterpret_cast<float4*>(sA + node * ASTRIDE + q * 4) = v;
        }
    }
    __syncthreads();

    int f = tid & 7;
    int g = tid >> 3;          // 0..15, nodes g*4 .. g*4+3

    float r0[4][8];
    // ---------------- GEMM hop 0 (f32x2) ----------------
    {
        unsigned long long acc2[4][4];
        #pragma unroll
        for (int i = 0; i < 4; ++i)
            #pragma unroll
            for (int j = 0; j < 4; ++j) acc2[i][j] = 0ull;

        #pragma unroll 2
        for (int k4 = 0; k4 < 16; ++k4) {
            float4 av[4];
            #pragma unroll
            for (int i = 0; i < 4; ++i)
                av[i] = *reinterpret_cast<const float4*>(sA + (g * 4 + i) * ASTRIDE + k4 * 4);
            #pragma unroll
            for (int kk = 0; kk < 4; ++kk) {
                int k = k4 * 4 + kk;
                ulonglong2 wl = *reinterpret_cast<const ulonglong2*>(sW + k * ASTRIDE + f * 4);
                ulonglong2 wh = *reinterpret_cast<const ulonglong2*>(sW + k * ASTRIDE + 32 + f * 4);
                #pragma unroll
                for (int i = 0; i < 4; ++i) {
                    float a = (kk == 0) ? av[i].x : (kk == 1) ? av[i].y
                            : (kk == 2) ? av[i].z : av[i].w;
                    unsigned long long pa = pack2(a);
                    acc2[i][0] = fma2(pa, wl.x, acc2[i][0]);
                    acc2[i][1] = fma2(pa, wl.y, acc2[i][1]);
                    acc2[i][2] = fma2(pa, wh.x, acc2[i][2]);
                    acc2[i][3] = fma2(pa, wh.y, acc2[i][3]);
                }
            }
        }
        const float* bb = sPar;
        const float* sc = sPar + 64;
        const float* of = sPar + 128;
        #pragma unroll
        for (int i = 0; i < 4; ++i) {
            float acc[8];
            unpack2(acc2[i][0], acc[0], acc[1]);
            unpack2(acc2[i][1], acc[2], acc[3]);
            unpack2(acc2[i][2], acc[4], acc[5]);
            unpack2(acc2[i][3], acc[6], acc[7]);
            float s = 0.f, q = 0.f;
            #pragma unroll
            for (int j = 0; j < 8; ++j) {
                int feat = (j < 4) ? (f * 4 + j) : (32 + f * 4 + j - 4);
                float h = fmaxf(acc[j] + bb[feat], 0.f);
                acc[j] = h;
                s += h;
                q = fmaf(h, h, q);
            }
            #pragma unroll
            for (int off = 1; off < 8; off <<= 1) {
                s += __shfl_xor_sync(0xffffffffu, s, off);
                q += __shfl_xor_sync(0xffffffffu, q, off);
            }
            float mean = s * (1.0f / 64.0f);
            float var  = q * (1.0f / 64.0f) - mean * mean + EPS;
            float rinv = rsqrtf(var);
            #pragma unroll
            for (int j = 0; j < 8; ++j) {
                int feat = (j < 4) ? (f * 4 + j) : (32 + f * 4 + j - 4);
                r0[i][j] = (acc[j] - mean) * sc[feat] * rinv + of[feat];
            }
        }
    }
    __syncthreads();

    // ---------------- reload: W1^T, agg tile ----------------
    {
        const float4* w4 = reinterpret_cast<const float4*>(g_WT1);
        for (int idx = tid; idx < 64 * 16; idx += 128) {
            int k = idx >> 4, c = idx & 15;
            *reinterpret_cast<float4*>(sW + k * ASTRIDE + c * 4) = __ldg(&w4[idx]);
        }
        const float4* a4 = reinterpret_cast<const float4*>(g_agg);
        for (int idx = tid; idx < 64 * 16; idx += 128) {
            int node = idx >> 4, q = idx & 15;
            int gnode = nodeBase + node;
            float4 v = make_float4(0.f, 0.f, 0.f, 0.f);
            if (gnode < nNodes) v = a4[gnode * 16 + q];
            *reinterpret_cast<float4*>(sA + node * ASTRIDE + q * 4) = v;
        }
    }
    __syncthreads();

    // ---------------- GEMM hop 1 (f32x2) + combine + store ----------------
    {
        unsigned long long acc2[4][4];
        #pragma unroll
        for (int i = 0; i < 4; ++i)
            #pragma unroll
            for (int j = 0; j < 4; ++j) acc2[i][j] = 0ull;

        #pragma unroll 2
        for (int k4 = 0; k4 < 16; ++k4) {
            float4 av[4];
            #pragma unroll
            for (int i = 0; i < 4; ++i)
                av[i] = *reinterpret_cast<const float4*>(sA + (g * 4 + i) * ASTRIDE + k4 * 4);
            #pragma unroll
            for (int kk = 0; kk < 4; ++kk) {
                int k = k4 * 4 + kk;
                ulonglong2 wl = *reinterpret_cast<const ulonglong2*>(sW + k * ASTRIDE + f * 4);
                ulonglong2 wh = *reinterpret_cast<const ulonglong2*>(sW + k * ASTRIDE + 32 + f * 4);
                #pragma unroll
                for (int i = 0; i < 4; ++i) {
                    float a = (kk == 0) ? av[i].x : (kk == 1) ? av[i].y
                            : (kk == 2) ? av[i].z : av[i].w;
                    unsigned long long pa = pack2(a);
                    acc2[i][0] = fma2(pa, wl.x, acc2[i][0]);
                    acc2[i][1] = fma2(pa, wl.y, acc2[i][1]);
                    acc2[i][2] = fma2(pa, wh.x, acc2[i][2]);
                    acc2[i][3] = fma2(pa, wh.y, acc2[i][3]);
                }
            }
        }
        const float* bb = sPar + 192;
        const float* sc = sPar + 256;
        const float* of = sPar + 320;
        #pragma unroll
        for (int i = 0; i < 4; ++i) {
            float acc[8];
            unpack2(acc2[i][0], acc[0], acc[1]);
            unpack2(acc2[i][1], acc[2], acc[3]);
            unpack2(acc2[i][2], acc[4], acc[5]);
            unpack2(acc2[i][3], acc[6], acc[7]);
            float s = 0.f, q = 0.f;
            #pragma unroll
            for (int j = 0; j < 8; ++j) {
                int feat = (j < 4) ? (f * 4 + j) : (32 + f * 4 + j - 4);
                float h = fmaxf(acc[j] + bb[feat], 0.f);
                acc[j] = h;
                s += h;
                q = fmaf(h, h, q);
            }
            #pragma unroll
            for (int off = 1; off < 8; off <<= 1) {
                s += __shfl_xor_sync(0xffffffffu, s, off);
                q += __shfl_xor_sync(0xffffffffu, q, off);
            }
            float mean = s * (1.0f / 64.0f);
            float var  = q * (1.0f / 64.0f) - mean * mean + EPS;
            float rinv = rsqrtf(var);

            int gnode = nodeBase + g * 4 + i;
            if (gnode < nNodes) {
                float lo[4], hi[4];
                #pragma unroll
                for (int j = 0; j < 4; ++j) {
                    int feat = f * 4 + j;
                    lo[j] = r0[i][j] + (acc[j] - mean) * sc[feat] * rinv + of[feat];
                }
                #pragma unroll
                for (int j = 0; j < 4; ++j) {
                    int feat = 32 + f * 4 + j;
                    hi[j] = r0[i][4 + j] + (acc[4 + j] - mean) * sc[feat] * rinv + of[feat];
                }
                float* op = out + (size_t)gnode * D;
                *reinterpret_cast<float4*>(op + f * 4)      = make_float4(lo[0], lo[1], lo[2], lo[3]);
                *reinterpret_cast<float4*>(op + 32 + f * 4) = make_float4(hi[0], hi[1], hi[2], hi[3]);
            }
        }
    }
}

// ---------------------------------------------------------------------------
// Launch: 5 kernels
// ---------------------------------------------------------------------------
extern "C" void kernel_launch(void* const* d_in, const int* in_sizes, int n_in,
                              void* d_out, int out_size) {
    const float* x        = (const float*)d_in[0];
    const float* edge_val = (const float*)d_in[1];
    const float* W0       = (const float*)d_in[2];
    const float* b0       = (const float*)d_in[3];
    const float* scale0   = (const float*)d_in[4];
    const float* offset0  = (const float*)d_in[5];
    const float* W1       = (const float*)d_in[6];
    const float* b1       = (const float*)d_in[7];
    const float* scale1   = (const float*)d_in[8];
    const float* offset1  = (const float*)d_in[9];
    const int*   edge_row = (const int*)d_in[10];
    const int*   edge_col = (const int*)d_in[11];
    float* out = (float*)d_out;

    int nNodes = in_sizes[0] / D;
    int E = in_sizes[1];

    int nHistThreads = (E + 3) / 4;
    hist_kernel<<<(nHistThreads + 255) / 256, 256>>>(edge_row, E);

    int nScanBlocks = (nNodes + SCAN_TILE - 1) / SCAN_TILE;   // 98 <= 148
    scan_kernel<<<nScanBlocks, 256>>>(W0, W1, nNodes, nScanBlocks);

    int nScatterThreads = (E + 3) / 4;
    edge_scatter_kernel<<<(nScatterThreads + 255) / 256, 256>>>(edge_row, edge_col,
                                                                edge_val, E);

    int grid_g = (nNodes * 8 + 255) / 256;
    gather_kernel<<<grid_g, 256>>>(x, nNodes);

    int grid_t = (nNodes + 63) / 64;
    transform_kernel<<<grid_t, 128>>>(x, b0, scale0, offset0,
                                      b1, scale1, offset1, out, nNodes);
}

// round 17
// speedup vs baseline: 1.4330x; 1.0780x over previous
#include <cuda_runtime.h>

#define MAX_NODES 100000
#define MAX_EDGES 1600000
#define D 64
#define EPS 1e-9f

#define SCAN_TILE 1024
#define MAX_SCAN_BLOCKS 128

// Scratch (no allocations allowed -> device globals)
static __device__ int   g_count[MAX_NODES];
static __device__ int   g_offset[MAX_NODES];
static __device__ int   g_rank[MAX_EDGES];      // per-edge rank within its row
static __device__ int   g_blockSums[MAX_SCAN_BLOCKS];
static __device__ int2  g_edges[MAX_EDGES];     // (col, val-as-int) CSR-sorted
static __device__ float g_agg[MAX_NODES * D];   // aggregated features
static __device__ float g_WT0[D * D];           // W0^T  [k][j]
static __device__ float g_WT1[D * D];           // W1^T  [k][j]

// ---- packed f32x2 helpers (sm_100+) ----
__device__ __forceinline__ unsigned long long fma2(unsigned long long a,
                                                   unsigned long long b,
                                                   unsigned long long c) {
    unsigned long long d;
    asm("fma.rn.f32x2 %0, %1, %2, %3;" : "=l"(d) : "l"(a), "l"(b), "l"(c));
    return d;
}
__device__ __forceinline__ unsigned long long pack2(float a) {
    unsigned long long r;
    asm("mov.b64 %0, {%1, %1};" : "=l"(r) : "f"(a));
    return r;
}
__device__ __forceinline__ void unpack2(unsigned long long v, float& lo, float& hi) {
    asm("mov.b64 {%0, %1}, %2;" : "=f"(lo), "=f"(hi) : "l"(v));
}

// ---------------------------------------------------------------------------
// Kernel 0: transpose weights + zero counters (merged)
// ---------------------------------------------------------------------------
__global__ void prep_kernel(const float* __restrict__ W0,
                            const float* __restrict__ W1, int nNodes) {
    int gid = blockIdx.x * blockDim.x + threadIdx.x;
    if (gid < D * D) {
        int j = gid >> 6, k = gid & 63;
        g_WT0[k * 64 + j] = W0[gid];
        g_WT1[k * 64 + j] = W1[gid];
    }
    for (int i = gid; i < nNodes; i += gridDim.x * blockDim.x)
        g_count[i] = 0;
}

// ---------------------------------------------------------------------------
// Kernel 1: histogram of edge_row; atomic returns the edge's rank
// ---------------------------------------------------------------------------
__global__ void hist_kernel(const int* __restrict__ edge_row, int E) {
    int e = blockIdx.x * blockDim.x + threadIdx.x;
    if (e < E) g_rank[e] = atomicAdd(&g_count[__ldg(edge_row + e)], 1);
}

// ---------------------------------------------------------------------------
// Scan phase A: per-block sum of SCAN_TILE counts
// ---------------------------------------------------------------------------
__global__ __launch_bounds__(256)
void scan_reduce_kernel(int nNodes) {
    __shared__ int warpSums[8];
    int b = blockIdx.x;
    int base = b * SCAN_TILE + threadIdx.x * 4;

    int s = 0;
    if (base + 3 < nNodes) {
        int4 v = *reinterpret_cast<const int4*>(g_count + base);
        s = v.x + v.y + v.z + v.w;
    } else {
        for (int i = 0; i < 4; ++i)
            if (base + i < nNodes) s += g_count[base + i];
    }
    #pragma unroll
    for (int off = 16; off; off >>= 1)
        s += __shfl_xor_sync(0xffffffffu, s, off);
    int lane = threadIdx.x & 31, warp = threadIdx.x >> 5;
    if (lane == 0) warpSums[warp] = s;
    __syncthreads();
    if (threadIdx.x == 0) {
        int t = 0;
        #pragma unroll
        for (int w = 0; w < 8; ++w) t += warpSums[w];
        g_blockSums[b] = t;
    }
}

// ---------------------------------------------------------------------------
// Scan phase B+C merged: per-block prefix of raw sums + write offsets
// ---------------------------------------------------------------------------
__global__ __launch_bounds__(256)
void scan_write_kernel(int nNodes, int nBlocks) {
    __shared__ int warpSums[8];
    __shared__ int sBS[MAX_SCAN_BLOCKS];
    int b = blockIdx.x;
    int tid = threadIdx.x;

    if (tid < nBlocks) sBS[tid] = g_blockSums[tid];
    __syncthreads();
    int blockPrefix = 0;
    for (int i = 0; i < b; ++i) blockPrefix += sBS[i];

    int base = b * SCAN_TILE + tid * 4;

    int c[4] = {0, 0, 0, 0};
    if (base + 3 < nNodes) {
        int4 v = *reinterpret_cast<const int4*>(g_count + base);
        c[0] = v.x; c[1] = v.y; c[2] = v.z; c[3] = v.w;
    } else {
        for (int i = 0; i < 4; ++i)
            if (base + i < nNodes) c[i] = g_count[base + i];
    }
    int local = c[0] + c[1] + c[2] + c[3];

    int lane = tid & 31, warp = tid >> 5;
    int p = local;
    #pragma unroll
    for (int off = 1; off < 32; off <<= 1) {
        int t = __shfl_up_sync(0xffffffffu, p, off);
        if (lane >= off) p += t;
    }
    if (lane == 31) warpSums[warp] = p;
    __syncthreads();
    int warpBase = 0;
    for (int w = 0; w < warp; ++w) warpBase += warpSums[w];
    int run = blockPrefix + warpBase + (p - local);

    int o[4];
    o[0] = run;
    o[1] = o[0] + c[0];
    o[2] = o[1] + c[1];
    o[3] = o[2] + c[2];
    if (base + 3 < nNodes) {
        *reinterpret_cast<int4*>(g_offset + base) = make_int4(o[0], o[1], o[2], o[3]);
    } else {
        for (int i = 0; i < 4; ++i)
            if (base + i < nNodes) g_offset[base + i] = o[i];
    }
}

// ---------------------------------------------------------------------------
// Kernel 4: scatter edges into CSR order — atomic-free, 4 edges/thread
// ---------------------------------------------------------------------------
__global__ __launch_bounds__(256)
void edge_scatter_kernel(const int* __restrict__ edge_row,
                         const int* __restrict__ edge_col,
                         const float* __restrict__ edge_val,
                         int E) {
    int t = blockIdx.x * blockDim.x + threadIdx.x;
    int e = t * 4;
    if (e + 3 < E) {
        int4 r4 = __ldg(reinterpret_cast<const int4*>(edge_row + e));
        int4 k4 = __ldg(reinterpret_cast<const int4*>(g_rank + e));
        int4 c4 = __ldg(reinterpret_cast<const int4*>(edge_col + e));
        float4 v4 = __ldg(reinterpret_cast<const float4*>(edge_val + e));
        int p0 = __ldg(&g_offset[r4.x]) + k4.x;
        int p1 = __ldg(&g_offset[r4.y]) + k4.y;
        int p2 = __ldg(&g_offset[r4.z]) + k4.z;
        int p3 = __ldg(&g_offset[r4.w]) + k4.w;
        g_edges[p0] = make_int2(c4.x, __float_as_int(v4.x));
        g_edges[p1] = make_int2(c4.y, __float_as_int(v4.y));
        g_edges[p2] = make_int2(c4.z, __float_as_int(v4.z));
        g_edges[p3] = make_int2(c4.w, __float_as_int(v4.w));
    } else {
        for (int i = e; i < E; ++i) {
            int r = __ldg(edge_row + i);
            int pos = __ldg(&g_offset[r]) + g_rank[i];
            g_edges[pos] = make_int2(__ldg(edge_col + i),
                                     __float_as_int(__ldg(edge_val + i)));
        }
    }
}

// ---------------------------------------------------------------------------
// Kernel 5: gather-SpMM, high-MLP mainloop.
//   8 threads/node (warp octet), 8 feats each. Per 8-edge batch:
//   phase 1 = 1 edge load + 16 shfls (all cols/vals to registers);
//   phase 2 = two waves of 4 edges, each wave issues 8 independent LDG.128
//   before any FMA consumes them.
// ---------------------------------------------------------------------------
__global__ __launch_bounds__(256)
void gather_kernel(const float* __restrict__ x, int nNodes) {
    int gid = blockIdx.x * 256 + threadIdx.x;
    int node = gid >> 3;
    int p = gid & 7;
    if (node >= nNodes) return;

    int lane = threadIdx.x & 31;
    unsigned gmask = 0xFFu << (lane & 24);

    int start = g_offset[node];
    int cnt   = g_count[node];
    const float4* x4 = reinterpret_cast<const float4*>(x);

    float4 acc0 = make_float4(0.f, 0.f, 0.f, 0.f);
    float4 acc1 = make_float4(0.f, 0.f, 0.f, 0.f);

    int base = 0;
    for (; base + 8 <= cnt; base += 8) {
        int2 ev = __ldg(&g_edges[start + base + p]);
        int   c0 = __shfl_sync(gmask, ev.x, 0, 8);
        int   c1 = __shfl_sync(gmask, ev.x, 1, 8);
        int   c2 = __shfl_sync(gmask, ev.x, 2, 8);
        int   c3 = __shfl_sync(gmask, ev.x, 3, 8);
        int   c4 = __shfl_sync(gmask, ev.x, 4, 8);
        int   c5 = __shfl_sync(gmask, ev.x, 5, 8);
        int   c6 = __shfl_sync(gmask, ev.x, 6, 8);
        int   c7 = __shfl_sync(gmask, ev.x, 7, 8);
        float v0 = __int_as_float(__shfl_sync(gmask, ev.y, 0, 8));
        float v1 = __int_as_float(__shfl_sync(gmask, ev.y, 1, 8));
        float v2 = __int_as_float(__shfl_sync(gmask, ev.y, 2, 8));
        float v3 = __int_as_float(__shfl_sync(gmask, ev.y, 3, 8));
        float v4 = __int_as_float(__shfl_sync(gmask, ev.y, 4, 8));
        float v5 = __int_as_float(__shfl_sync(gmask, ev.y, 5, 8));
        float v6 = __int_as_float(__shfl_sync(gmask, ev.y, 6, 8));
        float v7 = __int_as_float(__shfl_sync(gmask, ev.y, 7, 8));

        // ---- wave A: edges 0..3, 8 independent loads ----
        float4 a0 = __ldg(&x4[c0 * 16 + p * 2]);
        float4 b0 = __ldg(&x4[c0 * 16 + p * 2 + 1]);
        float4 a1 = __ldg(&x4[c1 * 16 + p * 2]);
        float4 b1 = __ldg(&x4[c1 * 16 + p * 2 + 1]);
        float4 a2 = __ldg(&x4[c2 * 16 + p * 2]);
        float4 b2 = __ldg(&x4[c2 * 16 + p * 2 + 1]);
        float4 a3 = __ldg(&x4[c3 * 16 + p * 2]);
        float4 b3 = __ldg(&x4[c3 * 16 + p * 2 + 1]);
        acc0.x = fmaf(v0, a0.x, acc0.x); acc0.y = fmaf(v0, a0.y, acc0.y);
        acc0.z = fmaf(v0, a0.z, acc0.z); acc0.w = fmaf(v0, a0.w, acc0.w);
        acc1.x = fmaf(v0, b0.x, acc1.x); acc1.y = fmaf(v0, b0.y, acc1.y);
        acc1.z = fmaf(v0, b0.z, acc1.z); acc1.w = fmaf(v0, b0.w, acc1.w);
        acc0.x = fmaf(v1, a1.x, acc0.x); acc0.y = fmaf(v1, a1.y, acc0.y);
        acc0.z = fmaf(v1, a1.z, acc0.z); acc0.w = fmaf(v1, a1.w, acc0.w);
        acc1.x = fmaf(v1, b1.x, acc1.x); acc1.y = fmaf(v1, b1.y, acc1.y);
        acc1.z = fmaf(v1, b1.z, acc1.z); acc1.w = fmaf(v1, b1.w, acc1.w);
        acc0.x = fmaf(v2, a2.x, acc0.x); acc0.y = fmaf(v2, a2.y, acc0.y);
        acc0.z = fmaf(v2, a2.z, acc0.z); acc0.w = fmaf(v2, a2.w, acc0.w);
        acc1.x = fmaf(v2, b2.x, acc1.x); acc1.y = fmaf(v2, b2.y, acc1.y);
        acc1.z = fmaf(v2, b2.z, acc1.z); acc1.w = fmaf(v2, b2.w, acc1.w);
        acc0.x = fmaf(v3, a3.x, acc0.x); acc0.y = fmaf(v3, a3.y, acc0.y);
        acc0.z = fmaf(v3, a3.z, acc0.z); acc0.w = fmaf(v3, a3.w, acc0.w);
        acc1.x = fmaf(v3, b3.x, acc1.x); acc1.y = fmaf(v3, b3.y, acc1.y);
        acc1.z = fmaf(v3, b3.z, acc1.z); acc1.w = fmaf(v3, b3.w, acc1.w);

        // ---- wave B: edges 4..7, 8 independent loads ----
        float4 a4 = __ldg(&x4[c4 * 16 + p * 2]);
        float4 b4 = __ldg(&x4[c4 * 16 + p * 2 + 1]);
        float4 a5 = __ldg(&x4[c5 * 16 + p * 2]);
        float4 b5 = __ldg(&x4[c5 * 16 + p * 2 + 1]);
        float4 a6 = __ldg(&x4[c6 * 16 + p * 2]);
        float4 b6 = __ldg(&x4[c6 * 16 + p * 2 + 1]);
        float4 a7 = __ldg(&x4[c7 * 16 + p * 2]);
        float4 b7 = __ldg(&x4[c7 * 16 + p * 2 + 1]);
        acc0.x = fmaf(v4, a4.x, acc0.x); acc0.y = fmaf(v4, a4.y, acc0.y);
        acc0.z = fmaf(v4, a4.z, acc0.z); acc0.w = fmaf(v4, a4.w, acc0.w);
        acc1.x = fmaf(v4, b4.x, acc1.x); acc1.y = fmaf(v4, b4.y, acc1.y);
        acc1.z = fmaf(v4, b4.z, acc1.z); acc1.w = fmaf(v4, b4.w, acc1.w);
        acc0.x = fmaf(v5, a5.x, acc0.x); acc0.y = fmaf(v5, a5.y, acc0.y);
        acc0.z = fmaf(v5, a5.z, acc0.z); acc0.w = fmaf(v5, a5.w, acc0.w);
        acc1.x = fmaf(v5, b5.x, acc1.x); acc1.y = fmaf(v5, b5.y, acc1.y);
        acc1.z = fmaf(v5, b5.z, acc1.z); acc1.w = fmaf(v5, b5.w, acc1.w);
        acc0.x = fmaf(v6, a6.x, acc0.x); acc0.y = fmaf(v6, a6.y, acc0.y);
        acc0.z = fmaf(v6, a6.z, acc0.z); acc0.w = fmaf(v6, a6.w, acc0.w);
        acc1.x = fmaf(v6, b6.x, acc1.x); acc1.y = fmaf(v6, b6.y, acc1.y);
        acc1.z = fmaf(v6, b6.z, acc1.z); acc1.w = fmaf(v6, b6.w, acc1.w);
        acc0.x = fmaf(v7, a7.x, acc0.x); acc0.y = fmaf(v7, a7.y, acc0.y);
        acc0.z = fmaf(v7, a7.z, acc0.z); acc0.w = fmaf(v7, a7.w, acc0.w);
        acc1.x = fmaf(v7, b7.x, acc1.x); acc1.y = fmaf(v7, b7.y, acc1.y);
        acc1.z = fmaf(v7, b7.z, acc1.z); acc1.w = fmaf(v7, b7.w, acc1.w);
    }

    // tail (< 8 edges), masked shfl loop
    if (base < cnt) {
        int idx = base + p;
        int2 ev = (idx < cnt) ? __ldg(&g_edges[start + idx]) : make_int2(0, 0);
        int m = cnt - base;
        for (int t = 0; t < m; ++t) {
            int   col = __shfl_sync(gmask, ev.x, t, 8);
            float v   = __int_as_float(__shfl_sync(gmask, ev.y, t, 8));
            float4 a = __ldg(&x4[col * 16 + p * 2]);
            float4 b = __ldg(&x4[col * 16 + p * 2 + 1]);
            acc0.x = fmaf(v, a.x, acc0.x); acc0.y = fmaf(v, a.y, acc0.y);
            acc0.z = fmaf(v, a.z, acc0.z); acc0.w = fmaf(v, a.w, acc0.w);
            acc1.x = fmaf(v, b.x, acc1.x); acc1.y = fmaf(v, b.y, acc1.y);
            acc1.z = fmaf(v, b.z, acc1.z); acc1.w = fmaf(v, b.w, acc1.w);
        }
    }

    float4* dst = reinterpret_cast<float4*>(g_agg + node * D + p * 8);
    dst[0] = acc0;
    dst[1] = acc1;
}

// ---------------------------------------------------------------------------
// Kernel 6: dual hop transform with packed f32x2 FMA (R12 version).
// ---------------------------------------------------------------------------
#define ASTRIDE 68

__global__ __launch_bounds__(128)
void transform_kernel(const float* __restrict__ x,
                      const float* __restrict__ b0, const float* __restrict__ s0,
                      const float* __restrict__ o0,
                      const float* __restrict__ b1, const float* __restrict__ s1,
                      const float* __restrict__ o1,
                      float* __restrict__ out, int nNodes) {
    __shared__ float sA[64 * ASTRIDE];
    __shared__ float sW[64 * ASTRIDE];
    __shared__ float sPar[6 * D];

    int tid = threadIdx.x;
    int nodeBase = blockIdx.x * 64;

    for (int idx = tid; idx < 6 * D; idx += 128) {
        int which = idx >> 6, t = idx & 63;
        const float* src = (which == 0) ? b0 : (which == 1) ? s0 : (which == 2) ? o0
                         : (which == 3) ? b1 : (which == 4) ? s1 : o1;
        sPar[idx] = src[t];
    }
    {
        const float4* w4 = reinterpret_cast<const float4*>(g_WT0);
        for (int idx = tid; idx < 64 * 16; idx += 128) {
            int k = idx >> 4, c = idx & 15;
            *reinterpret_cast<float4*>(sW + k * ASTRIDE + c * 4) = __ldg(&w4[idx]);
        }
        const float4* x4 = reinterpret_cast<const float4*>(x);
        for (int idx = tid; idx < 64 * 16; idx += 128) {
            int node = idx >> 4, q = idx & 15;
            int gnode = nodeBase + node;
            float4 v = make_float4(0.f, 0.f, 0.f, 0.f);
            if (gnode < nNodes) v = __ldg(&x4[gnode * 16 + q]);
            *reinterpret_cast<float4*>(sA + node * ASTRIDE + q * 4) = v;
        }
    }
    __syncthreads();

    int f = tid & 7;
    int g = tid >> 3;          // 0..15, nodes g*4 .. g*4+3

    float r0[4][8];
    // ---------------- GEMM hop 0 (f32x2) ----------------
    {
        unsigned long long acc2[4][4];
        #pragma unroll
        for (int i = 0; i < 4; ++i)
            #pragma unroll
            for (int j = 0; j < 4; ++j) acc2[i][j] = 0ull;

        #pragma unroll 2
        for (int k4 = 0; k4 < 16; ++k4) {
            float4 av[4];
            #pragma unroll
            for (int i = 0; i < 4; ++i)
                av[i] = *reinterpret_cast<const float4*>(sA + (g * 4 + i) * ASTRIDE + k4 * 4);
            #pragma unroll
            for (int kk = 0; kk < 4; ++kk) {
                int k = k4 * 4 + kk;
                ulonglong2 wl = *reinterpret_cast<const ulonglong2*>(sW + k * ASTRIDE + f * 4);
                ulonglong2 wh = *reinterpret_cast<const ulonglong2*>(sW + k * ASTRIDE + 32 + f * 4);
                #pragma unroll
                for (int i = 0; i < 4; ++i) {
                    float a = (kk == 0) ? av[i].x : (kk == 1) ? av[i].y
                            : (kk == 2) ? av[i].z : av[i].w;
                    unsigned long long pa = pack2(a);
                    acc2[i][0] = fma2(pa, wl.x, acc2[i][0]);
                    acc2[i][1] = fma2(pa, wl.y, acc2[i][1]);
                    acc2[i][2] = fma2(pa, wh.x, acc2[i][2]);
                    acc2[i][3] = fma2(pa, wh.y, acc2[i][3]);
                }
            }
        }
        const float* bb = sPar;
        const float* sc = sPar + 64;
        const float* of = sPar + 128;
        #pragma unroll
        for (int i = 0; i < 4; ++i) {
            float acc[8];
            unpack2(acc2[i][0], acc[0], acc[1]);
            unpack2(acc2[i][1], acc[2], acc[3]);
            unpack2(acc2[i][2], acc[4], acc[5]);
            unpack2(acc2[i][3], acc[6], acc[7]);
            float s = 0.f, q = 0.f;
            #pragma unroll
            for (int j = 0; j < 8; ++j) {
                int feat = (j < 4) ? (f * 4 + j) : (32 + f * 4 + j - 4);
                float h = fmaxf(acc[j] + bb[feat], 0.f);
                acc[j] = h;
                s += h;
                q = fmaf(h, h, q);
            }
            #pragma unroll
            for (int off = 1; off < 8; off <<= 1) {
                s += __shfl_xor_sync(0xffffffffu, s, off);
                q += __shfl_xor_sync(0xffffffffu, q, off);
            }
            float mean = s * (1.0f / 64.0f);
            float var  = q * (1.0f / 64.0f) - mean * mean + EPS;
            float rinv = rsqrtf(var);
            #pragma unroll
            for (int j = 0; j < 8; ++j) {
                int feat = (j < 4) ? (f * 4 + j) : (32 + f * 4 + j - 4);
                r0[i][j] = (acc[j] - mean) * sc[feat] * rinv + of[feat];
            }
        }
    }
    __syncthreads();

    // ---------------- reload: W1^T, agg tile ----------------
    {
        const float4* w4 = reinterpret_cast<const float4*>(g_WT1);
        for (int idx = tid; idx < 64 * 16; idx += 128) {
            int k = idx >> 4, c = idx & 15;
            *reinterpret_cast<float4*>(sW + k * ASTRIDE + c * 4) = __ldg(&w4[idx]);
        }
        const float4* a4 = reinterpret_cast<const float4*>(g_agg);
        for (int idx = tid; idx < 64 * 16; idx += 128) {
            int node = idx >> 4, q = idx & 15;
            int gnode = nodeBase + node;
            float4 v = make_float4(0.f, 0.f, 0.f, 0.f);
            if (gnode < nNodes) v = a4[gnode * 16 + q];
            *reinterpret_cast<float4*>(sA + node * ASTRIDE + q * 4) = v;
        }
    }
    __syncthreads();

    // ---------------- GEMM hop 1 (f32x2) + combine + store ----------------
    {
        unsigned long long acc2[4][4];
        #pragma unroll
        for (int i = 0; i < 4; ++i)
            #pragma unroll
            for (int j = 0; j < 4; ++j) acc2[i][j] = 0ull;

        #pragma unroll 2
        for (int k4 = 0; k4 < 16; ++k4) {
            float4 av[4];
            #pragma unroll
            for (int i = 0; i < 4; ++i)
                av[i] = *reinterpret_cast<const float4*>(sA + (g * 4 + i) * ASTRIDE + k4 * 4);
            #pragma unroll
            for (int kk = 0; kk < 4; ++kk) {
                int k = k4 * 4 + kk;
                ulonglong2 wl = *reinterpret_cast<const ulonglong2*>(sW + k * ASTRIDE + f * 4);
                ulonglong2 wh = *reinterpret_cast<const ulonglong2*>(sW + k * ASTRIDE + 32 + f * 4);
                #pragma unroll
                for (int i = 0; i < 4; ++i) {
                    float a = (kk == 0) ? av[i].x : (kk == 1) ? av[i].y
                            : (kk == 2) ? av[i].z : av[i].w;
                    unsigned long long pa = pack2(a);
                    acc2[i][0] = fma2(pa, wl.x, acc2[i][0]);
                    acc2[i][1] = fma2(pa, wl.y, acc2[i][1]);
                    acc2[i][2] = fma2(pa, wh.x, acc2[i][2]);
                    acc2[i][3] = fma2(pa, wh.y, acc2[i][3]);
                }
            }
        }
        const float* bb = sPar + 192;
        const float* sc = sPar + 256;
        const float* of = sPar + 320;
        #pragma unroll
        for (int i = 0; i < 4; ++i) {
            float acc[8];
            unpack2(acc2[i][0], acc[0], acc[1]);
            unpack2(acc2[i][1], acc[2], acc[3]);
            unpack2(acc2[i][2], acc[4], acc[5]);
            unpack2(acc2[i][3], acc[6], acc[7]);
            float s = 0.f, q = 0.f;
            #pragma unroll
            for (int j = 0; j < 8; ++j) {
                int feat = (j < 4) ? (f * 4 + j) : (32 + f * 4 + j - 4);
                float h = fmaxf(acc[j] + bb[feat], 0.f);
                acc[j] = h;
                s += h;
                q = fmaf(h, h, q);
            }
            #pragma unroll
            for (int off = 1; off < 8; off <<= 1) {
                s += __shfl_xor_sync(0xffffffffu, s, off);
                q += __shfl_xor_sync(0xffffffffu, q, off);
            }
            float mean = s * (1.0f / 64.0f);
            float var  = q * (1.0f / 64.0f) - mean * mean + EPS;
            float rinv = rsqrtf(var);

            int gnode = nodeBase + g * 4 + i;
            if (gnode < nNodes) {
                float lo[4], hi[4];
                #pragma unroll
                for (int j = 0; j < 4; ++j) {
                    int feat = f * 4 + j;
                    lo[j] = r0[i][j] + (acc[j] - mean) * sc[feat] * rinv + of[feat];
                }
                #pragma unroll
                for (int j = 0; j < 4; ++j) {
                    int feat = 32 + f * 4 + j;
                    hi[j] = r0[i][4 + j] + (acc[4 + j] - mean) * sc[feat] * rinv + of[feat];
                }
                float* op = out + (size_t)gnode * D;
                *reinterpret_cast<float4*>(op + f * 4)      = make_float4(lo[0], lo[1], lo[2], lo[3]);
                *reinterpret_cast<float4*>(op + 32 + f * 4) = make_float4(hi[0], hi[1], hi[2], hi[3]);
            }
        }
    }
}

// ---------------------------------------------------------------------------
// Launch (R12-proven structure)
// ---------------------------------------------------------------------------
extern "C" void kernel_launch(void* const* d_in, const int* in_sizes, int n_in,
                              void* d_out, int out_size) {
    const float* x        = (const float*)d_in[0];
    const float* edge_val = (const float*)d_in[1];
    const float* W0       = (const float*)d_in[2];
    const float* b0       = (const float*)d_in[3];
    const float* scale0   = (const float*)d_in[4];
    const float* offset0  = (const float*)d_in[5];
    const float* W1       = (const float*)d_in[6];
    const float* b1       = (const float*)d_in[7];
    const float* scale1   = (const float*)d_in[8];
    const float* offset1  = (const float*)d_in[9];
    const int*   edge_row = (const int*)d_in[10];
    const int*   edge_col = (const int*)d_in[11];
    float* out = (float*)d_out;

    int nNodes = in_sizes[0] / D;
    int E = in_sizes[1];

    prep_kernel<<<64, 256>>>(W0, W1, nNodes);
    hist_kernel<<<(E + 255) / 256, 256>>>(edge_row, E);

    int nScanBlocks = (nNodes + SCAN_TILE - 1) / SCAN_TILE;
    scan_reduce_kernel<<<nScanBlocks, 256>>>(nNodes);
    scan_write_kernel<<<nScanBlocks, 256>>>(nNodes, nScanBlocks);

    int nScatterThreads = (E + 3) / 4;
    edge_scatter_kernel<<<(nScatterThreads + 255) / 256, 256>>>(edge_row, edge_col,
                                                                edge_val, E);

    int grid_g = (nNodes * 8 + 255) / 256;
    gather_kernel<<<grid_g, 256>>>(x, nNodes);

    int grid_t = (nNodes + 63) / 64;
    transform_kernel<<<grid_t, 128>>>(x, b0, scale0, offset0,
                                      b1, scale1, offset1, out, nNodes);
}